// round 15
// baseline (speedup 1.0000x reference)
#include <cuda_runtime.h>
#include <cuda_fp16.h>
#include <cstdint>

#define BT 64
#define CH 64
#define LL 1024
#define BM 128
#define BN 64
#define NT (LL/BN)

// Scratch, all [b][c][l], single fp16 each.
__device__ __half g_q[(size_t)BT*CH*LL];
__device__ __half g_k[(size_t)BT*CH*LL];
__device__ __half g_v[(size_t)BT*CH*LL];

// ---------------- helpers ----------------
__device__ __forceinline__ uint32_t cvta_smem(const void* p) {
    uint32_t a;
    asm("{ .reg .u64 t; cvta.to.shared.u64 t, %1; cvt.u32.u64 %0, t; }" : "=r"(a) : "l"(p));
    return a;
}
#define CP16(dst, src) \
    asm volatile("cp.async.cg.shared.global [%0], [%1], 16;" :: "r"(dst), "l"(src) : "memory")
#define CP_COMMIT() asm volatile("cp.async.commit_group;" ::: "memory")
#define CP_WAIT(n)  asm volatile("cp.async.wait_group %0;" :: "n"(n) : "memory")

#define LDSM4(r0, r1, r2, r3, addr) \
    asm volatile("ldmatrix.sync.aligned.m8n8.x4.shared.b16 {%0,%1,%2,%3}, [%4];" \
        : "=r"(r0), "=r"(r1), "=r"(r2), "=r"(r3) : "r"(addr))
#define LDSM4T(r0, r1, r2, r3, addr) \
    asm volatile("ldmatrix.sync.aligned.m8n8.x4.trans.shared.b16 {%0,%1,%2,%3}, [%4];" \
        : "=r"(r0), "=r"(r1), "=r"(r2), "=r"(r3) : "r"(addr))

#define MMA_FP(d, a, b0, b1) \
    asm volatile("mma.sync.aligned.m16n8k16.row.col.f32.f16.f16.f32 " \
        "{%0,%1,%2,%3}, {%4,%5,%6,%7}, {%8,%9}, {%0,%1,%2,%3};" \
        : "+f"((d)[0]), "+f"((d)[1]), "+f"((d)[2]), "+f"((d)[3]) \
        : "r"((a)[0]), "r"((a)[1]), "r"((a)[2]), "r"((a)[3]), "r"(b0), "r"(b1))

__device__ __forceinline__ uint32_t cvt_f16x2(float hi, float lo) {
    uint32_t d; asm("cvt.rn.f16x2.f32 %0, %1, %2;" : "=r"(d) : "f"(hi), "f"(lo)); return d;
}
__device__ __forceinline__ uint32_t ex2_f16x2(uint32_t a) {
    uint32_t d; asm("ex2.approx.f16x2 %0, %1;" : "=r"(d) : "r"(a)); return d;
}
__device__ __forceinline__ float2 ffma2(float2 a, float2 b, float2 c) {
    unsigned long long A = *reinterpret_cast<unsigned long long*>(&a);
    unsigned long long B = *reinterpret_cast<unsigned long long*>(&b);
    unsigned long long Cc = *reinterpret_cast<unsigned long long*>(&c);
    unsigned long long D;
    asm("fma.rn.f32x2 %0, %1, %2, %3;" : "=l"(D) : "l"(A), "l"(B), "l"(Cc));
    return *reinterpret_cast<float2*>(&D);
}
__device__ __forceinline__ uint32_t lo_f16x2(float a, float b, uint32_t hi) {
    __half2 h = *reinterpret_cast<__half2*>(&hi);
    float2 hf = __half22float2(h);
    return cvt_f16x2(b - hf.y, a - hf.x);
}

#define ONES16X2 0x3C003C00u
#define LOG2E    1.4426950408889634f
// SW128 swizzle for 128B rows (chunk ^= row&7) and 256B rows.
#define SWZ(o)    ((o) ^ (((o) >> 3) & 0x70))
#define SWZ256(o) ((o) ^ (((o) >> 4) & 0x70))

// ---------------------------------------------------------------------------
// Kernel 1 (v6): QKV projection on tensor cores (unchanged from R14 pass).
// ---------------------------------------------------------------------------
#define XH_OFF 0u
#define XL_OFF 17408u
#define WH_OFF 34816u
#define WL_OFF 62464u
#define QKV_SMEM 90112

__global__ __launch_bounds__(256, 2) void qkv_kernel(
    const float* __restrict__ x,
    const float* __restrict__ Wq, const float* __restrict__ bq,
    const float* __restrict__ Wk, const float* __restrict__ bk,
    const float* __restrict__ Wv, const float* __restrict__ bv)
{
    extern __shared__ char sm[];
    const uint32_t smb = cvta_smem(sm);
    const int b    = blockIdx.y;
    const int l0   = blockIdx.x * 128;
    const int tid  = threadIdx.x;
    const int w    = tid >> 5;
    const int lane = tid & 31;
    const int g    = lane >> 2;
    const int tc   = lane & 3;

    #pragma unroll
    for (int i = 0; i < 12; i++) {
        const int ci = tid + i * 256;
        const int r  = ci >> 4;
        const int c4 = ci & 15;
        const float* ws = (r < 64) ? Wq : ((r < 128) ? Wk : Wv);
        float4 wv = *reinterpret_cast<const float4*>(ws + (r & 63) * 64 + c4 * 4);
        uint32_t h0 = cvt_f16x2(wv.y, wv.x);
        uint32_t h1 = cvt_f16x2(wv.w, wv.z);
        uint32_t l0r = lo_f16x2(wv.x, wv.y, h0);
        uint32_t l1r = lo_f16x2(wv.z, wv.w, h1);
        const uint32_t off = (uint32_t)r * 144 + (uint32_t)c4 * 8;
        *reinterpret_cast<uint2*>(sm + WH_OFF + off) = make_uint2(h0, h1);
        *reinterpret_cast<uint2*>(sm + WL_OFF + off) = make_uint2(l0r, l1r);
    }

    #pragma unroll
    for (int i = 0; i < 8; i++) {
        const int ci = tid + i * 256;
        const int c  = ci >> 5;
        const int lq = ci & 31;
        float4 xv = *reinterpret_cast<const float4*>(
            x + ((size_t)b * CH + c) * LL + l0 + lq * 4);
        uint32_t h0 = cvt_f16x2(xv.y, xv.x);
        uint32_t h1 = cvt_f16x2(xv.w, xv.z);
        uint32_t l0r = lo_f16x2(xv.x, xv.y, h0);
        uint32_t l1r = lo_f16x2(xv.z, xv.w, h1);
        const uint32_t off = (uint32_t)c * 272 + (uint32_t)lq * 8;
        *reinterpret_cast<uint2*>(sm + XH_OFF + off) = make_uint2(h0, h1);
        *reinterpret_cast<uint2*>(sm + XL_OFF + off) = make_uint2(l0r, l1r);
    }
    __syncthreads();

    uint32_t bh[2][8], bl[2][8];
    #pragma unroll
    for (int nb = 0; nb < 2; nb++) {
        #pragma unroll
        for (int h = 0; h < 2; h++) {
            uint32_t a = smb + XH_OFF + (uint32_t)(h * 32 + lane) * 272
                       + (uint32_t)(w * 16 + nb * 8) * 2;
            LDSM4T(bh[nb][h*4+0], bh[nb][h*4+1], bh[nb][h*4+2], bh[nb][h*4+3], a);
            LDSM4T(bl[nb][h*4+0], bl[nb][h*4+1], bl[nb][h*4+2], bl[nb][h*4+3],
                   a + (XL_OFF - XH_OFF));
        }
    }

    const uint32_t arow = (uint32_t)(((lane >> 3) & 1) * 8 + (lane & 7));
    const uint32_t acol = (uint32_t)(((lane >> 4) & 1) * 16);

    #pragma unroll
    for (int m = 0; m < 3; m++) {
        float acc[4][2][4];
        #pragma unroll
        for (int mb = 0; mb < 4; mb++)
            #pragma unroll
            for (int nb = 0; nb < 2; nb++)
                #pragma unroll
                for (int r = 0; r < 4; r++) acc[mb][nb][r] = 0.f;

        #pragma unroll
        for (int mb = 0; mb < 4; mb++) {
            #pragma unroll
            for (int ks = 0; ks < 4; ks++) {
                uint32_t ah[4], al[4];
                uint32_t a = smb + WH_OFF
                           + ((uint32_t)(m * 64 + mb * 16) + arow) * 144
                           + (uint32_t)ks * 32 + acol;
                LDSM4(ah[0], ah[1], ah[2], ah[3], a);
                if (m < 2) LDSM4(al[0], al[1], al[2], al[3], a + (WL_OFF - WH_OFF));
                #pragma unroll
                for (int nb = 0; nb < 2; nb++) {
                    MMA_FP(acc[mb][nb], ah, bh[nb][2*ks], bh[nb][2*ks+1]);
                    if (m < 2) {
                        MMA_FP(acc[mb][nb], ah, bl[nb][2*ks], bl[nb][2*ks+1]);
                        MMA_FP(acc[mb][nb], al, bh[nb][2*ks], bh[nb][2*ks+1]);
                    }
                }
            }
        }

        const float* bias = (m == 0) ? bq : (m == 1 ? bk : bv);
        __half* dst = (m == 0) ? g_q : (m == 1 ? g_k : g_v);
        #pragma unroll
        for (int mb = 0; mb < 4; mb++) {
            const float bl0 = __ldg(bias + mb * 16 + g);
            const float bl1 = __ldg(bias + mb * 16 + 8 + g);
            #pragma unroll
            for (int nb = 0; nb < 2; nb++) {
                const int l = l0 + w * 16 + nb * 8 + tc * 2;
                uint32_t v0 = cvt_f16x2(acc[mb][nb][1] + bl0, acc[mb][nb][0] + bl0);
                uint32_t v1 = cvt_f16x2(acc[mb][nb][3] + bl1, acc[mb][nb][2] + bl1);
                *reinterpret_cast<uint32_t*>(
                    dst + ((size_t)b * CH + mb * 16 + g) * LL + l) = v0;
                *reinterpret_cast<uint32_t*>(
                    dst + ((size_t)b * CH + mb * 16 + 8 + g) * LL + l) = v1;
            }
        }
    }
}

// ---------------------------------------------------------------------------
// Kernel 2 (v4): HMMA flash attention, BM=128 (8 warps share KV buffers),
// swizzled rows (Q 256B, KV 128B), 3 KV buffers, one barrier/tile.
// ---------------------------------------------------------------------------
#define B0_OFF 16384u
#define TBUF   16384u
#define VOFF   8192u
#define SM_TOT (B0_OFF + 3u*TBUF)   // 65536

__device__ __forceinline__ void load_kv(uint32_t buf, int b, int j0, int tid) {
    #pragma unroll
    for (int t = tid; t < 512; t += 256) {
        int row = t >> 3, ch = t & 7;
        uint32_t o = SWZ((uint32_t)row * 128 + (uint32_t)ch * 16);
        const size_t e = ((size_t)b * CH + row) * LL + j0;
        CP16(buf + o,        (const char*)(g_k + e) + ch * 16);
        CP16(buf + VOFF + o, (const char*)(g_v + e) + ch * 16);
    }
}

__global__ __launch_bounds__(256, 2) void attn_kernel(float* __restrict__ out)
{
    extern __shared__ char sm[];
    const uint32_t smb = cvta_smem(sm);
    const int b    = blockIdx.y;
    const int i0   = blockIdx.x * BM;
    const int tid  = threadIdx.x;
    const int w    = tid >> 5;      // 0..7; warp owns i-rows [w*16, w*16+16)
    const int lane = tid & 31;
    const int g    = lane >> 2;
    const int tc   = lane & 3;

    // Q tile [64 c][128 i], swizzled 256B rows at offset 0.
    #pragma unroll
    for (int t = tid; t < 1024; t += 256) {
        int row = t >> 4, ch = t & 15;
        uint32_t o = SWZ256((uint32_t)row * 256 + (uint32_t)ch * 16);
        const size_t e = ((size_t)b * CH + row) * LL + i0;
        CP16(smb + o, (const char*)(g_q + e) + ch * 16);
    }
    CP_COMMIT();
    load_kv(smb + B0_OFF, b, 0, tid);           CP_COMMIT();
    load_kv(smb + B0_OFF + TBUF, b, BN, tid);   CP_COMMIT();

    CP_WAIT(2);
    __syncthreads();

    // Q A-fragments via ldmatrix.trans from swizzled 256B-row tile
    uint32_t qf[4][4];
    {
        const int lr   = lane & 7;
        const int csel = (lane >> 4) & 1;
        const int isel = (lane >> 3) & 1;
        #pragma unroll
        for (int ks = 0; ks < 4; ks++) {
            uint32_t row = (uint32_t)(ks * 16 + lr + csel * 8);
            uint32_t bc  = (uint32_t)(w * 16 + isel * 8) * 2;
            LDSM4T(qf[ks][0], qf[ks][1], qf[ks][2], qf[ks][3],
                   smb + SWZ256(row * 256 + bc));
        }
    }

    float oa[8][4];
    #pragma unroll
    for (int c = 0; c < 8; c++)
        #pragma unroll
        for (int r = 0; r < 4; r++) oa[c][r] = 0.f;
    float rsacc[4] = {0.f, 0.f, 0.f, 0.f};
    float m0 = -1e30f, m1 = -1e30f;

    #pragma unroll 1
    for (int jt = 0; jt < NT; jt++) {
        if (jt < NT - 1) CP_WAIT(1); else CP_WAIT(0);
        __syncthreads();   // publishes tile jt; retires all reads of tile jt-1

        if (jt < NT - 2) {
            load_kv(smb + B0_OFF + (uint32_t)((jt + 2) % 3) * TBUF, b, (jt + 2) * BN, tid);
            CP_COMMIT();
        }

        const uint32_t kb = smb + B0_OFF + (uint32_t)(jt % 3) * TBUF;

        // ---- S = q16 * k16 ----
        float s[8][4];
        #pragma unroll
        for (int jb = 0; jb < 8; jb++)
            #pragma unroll
            for (int r = 0; r < 4; r++) s[jb][r] = 0.f;

        #pragma unroll
        for (int jb = 0; jb < 8; jb++) {
            uint32_t khr[8];
            #pragma unroll
            for (int h = 0; h < 2; h++) {
                uint32_t row = (uint32_t)(h * 32 + lane);
                uint32_t a = kb + SWZ(row * 128 + (uint32_t)jb * 16);
                LDSM4T(khr[h*4+0], khr[h*4+1], khr[h*4+2], khr[h*4+3], a);
            }
            #pragma unroll
            for (int ks = 0; ks < 4; ks++)
                MMA_FP(s[jb], qf[ks], khr[2*ks], khr[2*ks+1]);
        }

        // ---- online softmax ----
        float mt0 = fmaxf(s[0][0], s[0][1]), mt1 = fmaxf(s[0][2], s[0][3]);
        #pragma unroll
        for (int jb = 1; jb < 8; jb++) {
            mt0 = fmaxf(mt0, fmaxf(s[jb][0], s[jb][1]));
            mt1 = fmaxf(mt1, fmaxf(s[jb][2], s[jb][3]));
        }
        mt0 = fmaxf(mt0, __shfl_xor_sync(0xffffffffu, mt0, 1));
        mt0 = fmaxf(mt0, __shfl_xor_sync(0xffffffffu, mt0, 2));
        mt1 = fmaxf(mt1, __shfl_xor_sync(0xffffffffu, mt1, 1));
        mt1 = fmaxf(mt1, __shfl_xor_sync(0xffffffffu, mt1, 2));

        const float M0 = fmaxf(m0, mt0);
        const float M1 = fmaxf(m1, mt1);
        const bool nochange = (M0 == m0) && (M1 == m1);
        if (!__all_sync(0xffffffffu, nochange)) {
            const float c0 = __expf(m0 - M0);
            const float c1 = __expf(m1 - M1);
            rsacc[0] *= c0;  rsacc[2] *= c1;
            #pragma unroll
            for (int cb = 0; cb < 8; cb++) {
                oa[cb][0] *= c0;  oa[cb][1] *= c0;
                oa[cb][2] *= c1;  oa[cb][3] *= c1;
            }
        }
        m0 = M0;  m1 = M1;

        // ---- P = 2^((s-M)*log2e) ----
        const float2 l2e = make_float2(LOG2E, LOG2E);
        const float2 mb0 = make_float2(-M0 * LOG2E, -M0 * LOG2E);
        const float2 mb1 = make_float2(-M1 * LOG2E, -M1 * LOG2E);
        uint32_t pf[4][4];
        #pragma unroll
        for (int jb = 0; jb < 8; jb++) {
            float2 t01 = ffma2(make_float2(s[jb][0], s[jb][1]), l2e, mb0);
            float2 t23 = ffma2(make_float2(s[jb][2], s[jb][3]), l2e, mb1);
            const int ks = jb >> 1, pos = (jb & 1) * 2;
            pf[ks][pos    ] = ex2_f16x2(cvt_f16x2(t01.y, t01.x));
            pf[ks][pos + 1] = ex2_f16x2(cvt_f16x2(t23.y, t23.x));
        }

        // ---- row sums via ones-MMA ----
        #pragma unroll
        for (int ks = 0; ks < 4; ks++)
            MMA_FP(rsacc, pf[ks], ONES16X2, ONES16X2);

        // ---- O += P V ----
        #pragma unroll
        for (int cb = 0; cb < 8; cb++) {
            #pragma unroll
            for (int kp = 0; kp < 2; kp++) {
                uint32_t row = (uint32_t)(cb * 8 + (lane & 7));
                uint32_t bc  = (uint32_t)((lane >> 3) * 16 + kp * 64);
                uint32_t vv[4];
                LDSM4(vv[0], vv[1], vv[2], vv[3], kb + VOFF + SWZ(row * 128 + bc));
                #pragma unroll
                for (int k2 = 0; k2 < 2; k2++)
                    MMA_FP(oa[cb], pf[kp*2 + k2], vv[k2*2], vv[k2*2+1]);
            }
        }
    }

    // ---- epilogue ----
    const float inv0 = 1.f / rsacc[0];
    const float inv1 = 1.f / rsacc[2];

    const int r0 = i0 + w * 16 + g;
    const int r1 = r0 + 8;
    #pragma unroll
    for (int cb = 0; cb < 8; cb++) {
        const int c = cb * 8 + tc * 2;
        float* p0 = out + ((size_t)b * CH + c) * LL;
        p0[r0]      = oa[cb][0] * inv0;
        p0[LL + r0] = oa[cb][1] * inv0;
        p0[r1]      = oa[cb][2] * inv1;
        p0[LL + r1] = oa[cb][3] * inv1;
    }
}

// ---------------------------------------------------------------------------
extern "C" void kernel_launch(void* const* d_in, const int* in_sizes, int n_in,
                              void* d_out, int out_size)
{
    (void)in_sizes; (void)n_in; (void)out_size;
    const float* x  = (const float*)d_in[0];
    const float* Wq = (const float*)d_in[1];
    const float* bq = (const float*)d_in[2];
    const float* Wk = (const float*)d_in[3];
    const float* bk = (const float*)d_in[4];
    const float* Wv = (const float*)d_in[5];
    const float* bv = (const float*)d_in[6];
    float* out = (float*)d_out;

    cudaFuncSetAttribute(qkv_kernel, cudaFuncAttributeMaxDynamicSharedMemorySize, QKV_SMEM);
    qkv_kernel<<<dim3(LL / 128, BT), 256, QKV_SMEM>>>(x, Wq, bq, Wk, bk, Wv, bv);

    cudaFuncSetAttribute(attn_kernel, cudaFuncAttributeMaxDynamicSharedMemorySize, SM_TOT);
    attn_kernel<<<dim3(LL / BM, BT), 256, SM_TOT>>>(out);
}

// round 16
// speedup vs baseline: 1.0847x; 1.0847x over previous
#include <cuda_runtime.h>
#include <cuda_fp16.h>
#include <cstdint>

#define BT 64
#define CH 64
#define LL 1024
#define BM 64
#define BN 64
#define NT (LL/BN)

// Scratch, all [b][c][l], single fp16 each.
__device__ __half g_q[(size_t)BT*CH*LL];
__device__ __half g_k[(size_t)BT*CH*LL];
__device__ __half g_v[(size_t)BT*CH*LL];

// ---------------- helpers ----------------
__device__ __forceinline__ uint32_t cvta_smem(const void* p) {
    uint32_t a;
    asm("{ .reg .u64 t; cvta.to.shared.u64 t, %1; cvt.u32.u64 %0, t; }" : "=r"(a) : "l"(p));
    return a;
}
#define CP16(dst, src) \
    asm volatile("cp.async.cg.shared.global [%0], [%1], 16;" :: "r"(dst), "l"(src) : "memory")
#define CP_COMMIT() asm volatile("cp.async.commit_group;" ::: "memory")
#define CP_WAIT(n)  asm volatile("cp.async.wait_group %0;" :: "n"(n) : "memory")

#define LDSM4(r0, r1, r2, r3, addr) \
    asm volatile("ldmatrix.sync.aligned.m8n8.x4.shared.b16 {%0,%1,%2,%3}, [%4];" \
        : "=r"(r0), "=r"(r1), "=r"(r2), "=r"(r3) : "r"(addr))
#define LDSM4T(r0, r1, r2, r3, addr) \
    asm volatile("ldmatrix.sync.aligned.m8n8.x4.trans.shared.b16 {%0,%1,%2,%3}, [%4];" \
        : "=r"(r0), "=r"(r1), "=r"(r2), "=r"(r3) : "r"(addr))

#define MMA_FP(d, a, b0, b1) \
    asm volatile("mma.sync.aligned.m16n8k16.row.col.f32.f16.f16.f32 " \
        "{%0,%1,%2,%3}, {%4,%5,%6,%7}, {%8,%9}, {%0,%1,%2,%3};" \
        : "+f"((d)[0]), "+f"((d)[1]), "+f"((d)[2]), "+f"((d)[3]) \
        : "r"((a)[0]), "r"((a)[1]), "r"((a)[2]), "r"((a)[3]), "r"(b0), "r"(b1))

__device__ __forceinline__ uint32_t cvt_f16x2(float hi, float lo) {
    uint32_t d; asm("cvt.rn.f16x2.f32 %0, %1, %2;" : "=r"(d) : "f"(hi), "f"(lo)); return d;
}
__device__ __forceinline__ uint32_t ex2_f16x2(uint32_t a) {
    uint32_t d; asm("ex2.approx.f16x2 %0, %1;" : "=r"(d) : "r"(a)); return d;
}
__device__ __forceinline__ float2 ffma2(float2 a, float2 b, float2 c) {
    unsigned long long A = *reinterpret_cast<unsigned long long*>(&a);
    unsigned long long B = *reinterpret_cast<unsigned long long*>(&b);
    unsigned long long Cc = *reinterpret_cast<unsigned long long*>(&c);
    unsigned long long D;
    asm("fma.rn.f32x2 %0, %1, %2, %3;" : "=l"(D) : "l"(A), "l"(B), "l"(Cc));
    return *reinterpret_cast<float2*>(&D);
}
__device__ __forceinline__ uint32_t lo_f16x2(float a, float b, uint32_t hi) {
    __half2 h = *reinterpret_cast<__half2*>(&hi);
    float2 hf = __half22float2(h);
    return cvt_f16x2(b - hf.y, a - hf.x);
}

#define ONES16X2 0x3C003C00u
#define LOG2E    1.4426950408889634f
// SW128 swizzle for 128B rows: chunk ^= row&7.
#define SWZ(o) ((o) ^ (((o) >> 3) & 0x70))

// ---------------------------------------------------------------------------
// Kernel 1 (v7): QKV projection on tensor cores, 128-l tiles / 256 threads.
// x: SINGLE fp16 (no lo). W: hi/lo. q,k = (Wh+Wl)*x (2 MMA); v = Wh*x (1 MMA).
// smem 72 KB -> 3 CTAs/SM.
// ---------------------------------------------------------------------------
#define XH_OFF 0u
#define WH_OFF 17408u
#define WL_OFF 45056u
#define QKV_SMEM 73728

__global__ __launch_bounds__(256, 3) void qkv_kernel(
    const float* __restrict__ x,
    const float* __restrict__ Wq, const float* __restrict__ bq,
    const float* __restrict__ Wk, const float* __restrict__ bk,
    const float* __restrict__ Wv, const float* __restrict__ bv)
{
    extern __shared__ char sm[];
    const uint32_t smb = cvta_smem(sm);
    const int b    = blockIdx.y;
    const int l0   = blockIdx.x * 128;
    const int tid  = threadIdx.x;
    const int w    = tid >> 5;
    const int lane = tid & 31;
    const int g    = lane >> 2;
    const int tc   = lane & 3;

    // ---- convert W (3 x 64x64 f32) -> fp16 hi/lo smem rows [o][c], 144B stride
    #pragma unroll
    for (int i = 0; i < 12; i++) {
        const int ci = tid + i * 256;
        const int r  = ci >> 4;
        const int c4 = ci & 15;
        const float* ws = (r < 64) ? Wq : ((r < 128) ? Wk : Wv);
        float4 wv = *reinterpret_cast<const float4*>(ws + (r & 63) * 64 + c4 * 4);
        uint32_t h0 = cvt_f16x2(wv.y, wv.x);
        uint32_t h1 = cvt_f16x2(wv.w, wv.z);
        uint32_t l0r = lo_f16x2(wv.x, wv.y, h0);
        uint32_t l1r = lo_f16x2(wv.z, wv.w, h1);
        const uint32_t off = (uint32_t)r * 144 + (uint32_t)c4 * 8;
        *reinterpret_cast<uint2*>(sm + WH_OFF + off) = make_uint2(h0, h1);
        *reinterpret_cast<uint2*>(sm + WL_OFF + off) = make_uint2(l0r, l1r);
    }

    // ---- convert x tile (64c x 128l f32) -> SINGLE fp16 smem rows, 272B stride
    #pragma unroll
    for (int i = 0; i < 8; i++) {
        const int ci = tid + i * 256;
        const int c  = ci >> 5;
        const int lq = ci & 31;
        float4 xv = *reinterpret_cast<const float4*>(
            x + ((size_t)b * CH + c) * LL + l0 + lq * 4);
        uint32_t h0 = cvt_f16x2(xv.y, xv.x);
        uint32_t h1 = cvt_f16x2(xv.w, xv.z);
        const uint32_t off = (uint32_t)c * 272 + (uint32_t)lq * 8;
        *reinterpret_cast<uint2*>(sm + XH_OFF + off) = make_uint2(h0, h1);
    }
    __syncthreads();

    // ---- B fragments (x), loaded once, reused for all 3 matrices ----
    uint32_t bh[2][8];
    #pragma unroll
    for (int nb = 0; nb < 2; nb++) {
        #pragma unroll
        for (int h = 0; h < 2; h++) {
            uint32_t a = smb + XH_OFF + (uint32_t)(h * 32 + lane) * 272
                       + (uint32_t)(w * 16 + nb * 8) * 2;
            LDSM4T(bh[nb][h*4+0], bh[nb][h*4+1], bh[nb][h*4+2], bh[nb][h*4+3], a);
        }
    }

    const uint32_t arow = (uint32_t)(((lane >> 3) & 1) * 8 + (lane & 7));
    const uint32_t acol = (uint32_t)(((lane >> 4) & 1) * 16);

    #pragma unroll
    for (int m = 0; m < 3; m++) {
        float acc[4][2][4];
        #pragma unroll
        for (int mb = 0; mb < 4; mb++)
            #pragma unroll
            for (int nb = 0; nb < 2; nb++)
                #pragma unroll
                for (int r = 0; r < 4; r++) acc[mb][nb][r] = 0.f;

        #pragma unroll
        for (int mb = 0; mb < 4; mb++) {
            #pragma unroll
            for (int ks = 0; ks < 4; ks++) {
                uint32_t ah[4], al[4];
                uint32_t a = smb + WH_OFF
                           + ((uint32_t)(m * 64 + mb * 16) + arow) * 144
                           + (uint32_t)ks * 32 + acol;
                LDSM4(ah[0], ah[1], ah[2], ah[3], a);
                if (m < 2) LDSM4(al[0], al[1], al[2], al[3], a + (WL_OFF - WH_OFF));
                #pragma unroll
                for (int nb = 0; nb < 2; nb++) {
                    MMA_FP(acc[mb][nb], ah, bh[nb][2*ks], bh[nb][2*ks+1]);
                    if (m < 2)
                        MMA_FP(acc[mb][nb], al, bh[nb][2*ks], bh[nb][2*ks+1]);
                }
            }
        }

        const float* bias = (m == 0) ? bq : (m == 1 ? bk : bv);
        __half* dst = (m == 0) ? g_q : (m == 1 ? g_k : g_v);
        #pragma unroll
        for (int mb = 0; mb < 4; mb++) {
            const float bl0 = __ldg(bias + mb * 16 + g);
            const float bl1 = __ldg(bias + mb * 16 + 8 + g);
            #pragma unroll
            for (int nb = 0; nb < 2; nb++) {
                const int l = l0 + w * 16 + nb * 8 + tc * 2;
                uint32_t v0 = cvt_f16x2(acc[mb][nb][1] + bl0, acc[mb][nb][0] + bl0);
                uint32_t v1 = cvt_f16x2(acc[mb][nb][3] + bl1, acc[mb][nb][2] + bl1);
                *reinterpret_cast<uint32_t*>(
                    dst + ((size_t)b * CH + mb * 16 + g) * LL + l) = v0;
                *reinterpret_cast<uint32_t*>(
                    dst + ((size_t)b * CH + mb * 16 + 8 + g) * LL + l) = v1;
            }
        }
    }
}

// ---------------------------------------------------------------------------
// Kernel 2 (v3 = R14, proven 57.4us): HMMA flash attention, SW128 swizzle,
// 3 KV buffers, one barrier/tile, prefetch before compute. BM=64, 128 thr.
// ---------------------------------------------------------------------------
#define B0_OFF 8192u
#define TBUF   16384u
#define VOFF   8192u
#define SM_TOT (B0_OFF + 3u*TBUF)   // 57344

__device__ __forceinline__ void load_kv(uint32_t buf, int b, int j0, int tid) {
    #pragma unroll
    for (int t = tid; t < 512; t += 128) {
        int row = t >> 3, ch = t & 7;
        uint32_t o = SWZ((uint32_t)row * 128 + (uint32_t)ch * 16);
        const size_t e = ((size_t)b * CH + row) * LL + j0;
        CP16(buf + o,        (const char*)(g_k + e) + ch * 16);
        CP16(buf + VOFF + o, (const char*)(g_v + e) + ch * 16);
    }
}

__global__ __launch_bounds__(128, 4) void attn_kernel(float* __restrict__ out)
{
    extern __shared__ char sm[];
    const uint32_t smb = cvta_smem(sm);
    const int b    = blockIdx.y;
    const int i0   = blockIdx.x * BM;
    const int tid  = threadIdx.x;
    const int w    = tid >> 5;
    const int lane = tid & 31;
    const int g    = lane >> 2;
    const int tc   = lane & 3;

    #pragma unroll
    for (int t = tid; t < 512; t += 128) {
        int row = t >> 3, ch = t & 7;
        uint32_t o = SWZ((uint32_t)row * 128 + (uint32_t)ch * 16);
        const size_t e = ((size_t)b * CH + row) * LL + i0;
        CP16(smb + o, (const char*)(g_q + e) + ch * 16);
    }
    CP_COMMIT();
    load_kv(smb + B0_OFF, b, 0, tid);           CP_COMMIT();
    load_kv(smb + B0_OFF + TBUF, b, BN, tid);   CP_COMMIT();

    CP_WAIT(2);
    __syncthreads();

    uint32_t qf[4][4];
    {
        const int lr   = lane & 7;
        const int csel = (lane >> 4) & 1;
        const int isel = (lane >> 3) & 1;
        #pragma unroll
        for (int ks = 0; ks < 4; ks++) {
            uint32_t row = (uint32_t)(ks * 16 + lr + csel * 8);
            uint32_t bc  = (uint32_t)(w * 16 + isel * 8) * 2;
            LDSM4T(qf[ks][0], qf[ks][1], qf[ks][2], qf[ks][3],
                   smb + SWZ(row * 128 + bc));
        }
    }

    float oa[8][4];
    #pragma unroll
    for (int c = 0; c < 8; c++)
        #pragma unroll
        for (int r = 0; r < 4; r++) oa[c][r] = 0.f;
    float rsacc[4] = {0.f, 0.f, 0.f, 0.f};
    float m0 = -1e30f, m1 = -1e30f;

    #pragma unroll 1
    for (int jt = 0; jt < NT; jt++) {
        if (jt < NT - 1) CP_WAIT(1); else CP_WAIT(0);
        __syncthreads();   // publishes tile jt; retires all reads of tile jt-1

        if (jt < NT - 2) {
            load_kv(smb + B0_OFF + (uint32_t)((jt + 2) % 3) * TBUF, b, (jt + 2) * BN, tid);
            CP_COMMIT();
        }

        const uint32_t kb = smb + B0_OFF + (uint32_t)(jt % 3) * TBUF;

        // ---- S = q16 * k16 ----
        float s[8][4];
        #pragma unroll
        for (int jb = 0; jb < 8; jb++)
            #pragma unroll
            for (int r = 0; r < 4; r++) s[jb][r] = 0.f;

        #pragma unroll
        for (int jb = 0; jb < 8; jb++) {
            uint32_t khr[8];
            #pragma unroll
            for (int h = 0; h < 2; h++) {
                uint32_t row = (uint32_t)(h * 32 + lane);
                uint32_t a = kb + SWZ(row * 128 + (uint32_t)jb * 16);
                LDSM4T(khr[h*4+0], khr[h*4+1], khr[h*4+2], khr[h*4+3], a);
            }
            #pragma unroll
            for (int ks = 0; ks < 4; ks++)
                MMA_FP(s[jb], qf[ks], khr[2*ks], khr[2*ks+1]);
        }

        // ---- online softmax ----
        float mt0 = fmaxf(s[0][0], s[0][1]), mt1 = fmaxf(s[0][2], s[0][3]);
        #pragma unroll
        for (int jb = 1; jb < 8; jb++) {
            mt0 = fmaxf(mt0, fmaxf(s[jb][0], s[jb][1]));
            mt1 = fmaxf(mt1, fmaxf(s[jb][2], s[jb][3]));
        }
        mt0 = fmaxf(mt0, __shfl_xor_sync(0xffffffffu, mt0, 1));
        mt0 = fmaxf(mt0, __shfl_xor_sync(0xffffffffu, mt0, 2));
        mt1 = fmaxf(mt1, __shfl_xor_sync(0xffffffffu, mt1, 1));
        mt1 = fmaxf(mt1, __shfl_xor_sync(0xffffffffu, mt1, 2));

        const float M0 = fmaxf(m0, mt0);
        const float M1 = fmaxf(m1, mt1);
        const bool nochange = (M0 == m0) && (M1 == m1);
        if (!__all_sync(0xffffffffu, nochange)) {
            const float c0 = __expf(m0 - M0);
            const float c1 = __expf(m1 - M1);
            rsacc[0] *= c0;  rsacc[2] *= c1;
            #pragma unroll
            for (int cb = 0; cb < 8; cb++) {
                oa[cb][0] *= c0;  oa[cb][1] *= c0;
                oa[cb][2] *= c1;  oa[cb][3] *= c1;
            }
        }
        m0 = M0;  m1 = M1;

        // ---- P = 2^((s-M)*log2e) ----
        const float2 l2e = make_float2(LOG2E, LOG2E);
        const float2 mb0 = make_float2(-M0 * LOG2E, -M0 * LOG2E);
        const float2 mb1 = make_float2(-M1 * LOG2E, -M1 * LOG2E);
        uint32_t pf[4][4];
        #pragma unroll
        for (int jb = 0; jb < 8; jb++) {
            float2 t01 = ffma2(make_float2(s[jb][0], s[jb][1]), l2e, mb0);
            float2 t23 = ffma2(make_float2(s[jb][2], s[jb][3]), l2e, mb1);
            const int ks = jb >> 1, pos = (jb & 1) * 2;
            pf[ks][pos    ] = ex2_f16x2(cvt_f16x2(t01.y, t01.x));
            pf[ks][pos + 1] = ex2_f16x2(cvt_f16x2(t23.y, t23.x));
        }

        // ---- row sums via ones-MMA ----
        #pragma unroll
        for (int ks = 0; ks < 4; ks++)
            MMA_FP(rsacc, pf[ks], ONES16X2, ONES16X2);

        // ---- O += P V ----
        #pragma unroll
        for (int cb = 0; cb < 8; cb++) {
            #pragma unroll
            for (int kp = 0; kp < 2; kp++) {
                uint32_t row = (uint32_t)(cb * 8 + (lane & 7));
                uint32_t bc  = (uint32_t)((lane >> 3) * 16 + kp * 64);
                uint32_t vv[4];
                LDSM4(vv[0], vv[1], vv[2], vv[3], kb + VOFF + SWZ(row * 128 + bc));
                #pragma unroll
                for (int k2 = 0; k2 < 2; k2++)
                    MMA_FP(oa[cb], pf[kp*2 + k2], vv[k2*2], vv[k2*2+1]);
            }
        }
    }

    // ---- epilogue ----
    const float inv0 = 1.f / rsacc[0];
    const float inv1 = 1.f / rsacc[2];

    const int r0 = i0 + w * 16 + g;
    const int r1 = r0 + 8;
    #pragma unroll
    for (int cb = 0; cb < 8; cb++) {
        const int c = cb * 8 + tc * 2;
        float* p0 = out + ((size_t)b * CH + c) * LL;
        p0[r0]      = oa[cb][0] * inv0;
        p0[LL + r0] = oa[cb][1] * inv0;
        p0[r1]      = oa[cb][2] * inv1;
        p0[LL + r1] = oa[cb][3] * inv1;
    }
}

// ---------------------------------------------------------------------------
extern "C" void kernel_launch(void* const* d_in, const int* in_sizes, int n_in,
                              void* d_out, int out_size)
{
    (void)in_sizes; (void)n_in; (void)out_size;
    const float* x  = (const float*)d_in[0];
    const float* Wq = (const float*)d_in[1];
    const float* bq = (const float*)d_in[2];
    const float* Wk = (const float*)d_in[3];
    const float* bk = (const float*)d_in[4];
    const float* Wv = (const float*)d_in[5];
    const float* bv = (const float*)d_in[6];
    float* out = (float*)d_out;

    cudaFuncSetAttribute(qkv_kernel, cudaFuncAttributeMaxDynamicSharedMemorySize, QKV_SMEM);
    qkv_kernel<<<dim3(LL / 128, BT), 256, QKV_SMEM>>>(x, Wq, bq, Wk, bk, Wv, bv);

    cudaFuncSetAttribute(attn_kernel, cudaFuncAttributeMaxDynamicSharedMemorySize, SM_TOT);
    attn_kernel<<<dim3(LL / BM, BT), 128, SM_TOT>>>(out);
}